// round 7
// baseline (speedup 1.0000x reference)
#include <cuda_runtime.h>
#include <cuda_bf16.h>
#include <cuda_fp16.h>
#include <cstdint>
#include <math.h>

#define NN 10000
#define NE 640000
#define DH 128
#define NL 3

// ---------------- scratch (static device globals; no allocs) ----------------
__device__ int    g_cnt[NN];
__device__ int    g_off[NN + 1];
__device__ int    g_pos[NE];
__device__ int2   g_edge[NE];          // packed (src, w-as-bits), CSR order by dst
__device__ float  g_tmpA[NN * DH];
__device__ float  g_tmpB[NN * DH];
__device__ __half g_Mh[NN * DH];       // fp16 message buffer
__device__ float  g_S[NN * DH];
__device__ float  g_scores[NL * NN];
__device__ float  g_Wt[13 * DH * DH];  // pre-transposed weights: Wt[n][k] = W[k][n]

// ---------------- preprocessing ---------------------------------------------
__global__ void zero_kernel() {
    int i = blockIdx.x * blockDim.x + threadIdx.x;
    if (i < NN) g_cnt[i] = 0;
    if (i < NL * NN) g_scores[i] = 0.f;
}

__global__ void count_kernel(const int* __restrict__ ei) {
    int e = blockIdx.x * blockDim.x + threadIdx.x;
    if (e < NE) g_pos[e] = atomicAdd(&g_cnt[ei[NE + e]], 1);
}

// 1024 threads, 10 elems/thread: sequential + warp scan + cross-warp scan
__global__ void scan_kernel() {
    __shared__ int wsum[32];
    int t = threadIdx.x;
    int lane = t & 31, w = t >> 5;
    int base = t * 10;
    int loc[10];
    int s = 0;
#pragma unroll
    for (int i = 0; i < 10; i++) {
        int idx = base + i;
        int c = (idx < NN) ? g_cnt[idx] : 0;
        loc[i] = s; s += c;
    }
    int inc = s;
#pragma unroll
    for (int o = 1; o < 32; o <<= 1) {
        int u = __shfl_up_sync(0xffffffffu, inc, o);
        if (lane >= o) inc += u;
    }
    if (lane == 31) wsum[w] = inc;
    __syncthreads();
    if (w == 0) {
        int ws = wsum[lane];
#pragma unroll
        for (int o = 1; o < 32; o <<= 1) {
            int u = __shfl_up_sync(0xffffffffu, ws, o);
            if (lane >= o) ws += u;
        }
        wsum[lane] = ws;
    }
    __syncthreads();
    int warp_excl = (w == 0) ? 0 : wsum[w - 1];
    int excl = warp_excl + (inc - s);
#pragma unroll
    for (int i = 0; i < 10; i++) {
        int idx = base + i;
        if (idx < NN) g_off[idx] = excl + loc[i];
    }
    if (t == 1023) g_off[NN] = warp_excl + inc;
}

__global__ void scatter_kernel(const int* __restrict__ ei, const float* __restrict__ conf) {
    int e = blockIdx.x * blockDim.x + threadIdx.x;
    if (e >= NE) return;
    int s = ei[e];
    int d = ei[NE + e];
    float w = expf(-fabsf(conf[s] - conf[d]));
    int p = g_off[d] + g_pos[e];
    g_edge[p] = make_int2(s, __float_as_int(w));
}

// ---------------- weight pre-transpose: Wt[n][k] = W[k][n] ------------------
__global__ void transpose_weights(const float* __restrict__ msgW1, const float* __restrict__ selfW1,
                                  const float* __restrict__ msgW2, const float* __restrict__ selfW2,
                                  const float* __restrict__ scoreW1) {
    __shared__ float tile[32][33];
    int m = blockIdx.z;
    const float* src;
    if (m < 3)       src = msgW1  + (long)m * DH * DH;
    else if (m < 6)  src = selfW1 + (long)(m - 3) * DH * DH;
    else if (m < 9)  src = msgW2  + (long)(m - 6) * DH * DH;
    else if (m < 12) src = selfW2 + (long)(m - 9) * DH * DH;
    else             src = scoreW1;
    float* dst = g_Wt + (long)m * DH * DH;

    int x = blockIdx.x * 32 + threadIdx.x;
    int y = blockIdx.y * 32 + threadIdx.y;
#pragma unroll
    for (int j = 0; j < 32; j += 8)
        tile[threadIdx.y + j][threadIdx.x] = src[(y + j) * DH + x];
    __syncthreads();
    x = blockIdx.y * 32 + threadIdx.x;
    y = blockIdx.x * 32 + threadIdx.y;
#pragma unroll
    for (int j = 0; j < 32; j += 8)
        dst[(y + j) * DH + x] = tile[threadIdx.x][threadIdx.y + j];
}

// ================= fused dual-output mma.sync bf16 3x-split GEMM ============
// Two independent GEMMs in one launch (blockIdx < nblk0 -> half 0).
// C[M,128] = A[M,128] @ W[128,128] (+bias); Bt row-major [n][k] = W^T.
// mode 0: bias+relu fp32; mode 1: bias fp32; mode 2: relu(+bias) dot w2 -> scores (atomic);
// mode 3: bias fp16 store.
#define STRB 272
#define TILE_BYTES (128 * STRB)
#define SM_BIAS  0
#define SM_W2    512
#define SM_A_HI  1024
#define SM_A_LO  (SM_A_HI + TILE_BYTES)
#define SM_B_HI  (SM_A_LO + TILE_BYTES)
#define SM_B_LO  (SM_B_HI + TILE_BYTES)
#define SM_TOTAL (SM_B_LO + TILE_BYTES)

#define LDSM_X4(r0, r1, r2, r3, addr) \
    asm volatile("ldmatrix.sync.aligned.m8n8.x4.shared.b16 {%0,%1,%2,%3}, [%4];" \
        : "=r"(r0), "=r"(r1), "=r"(r2), "=r"(r3) : "r"(addr))

#define MMA16816(d, a0, a1, a2, a3, b0, b1) \
    asm volatile("mma.sync.aligned.m16n8k16.row.col.f32.bf16.bf16.f32 " \
        "{%0,%1,%2,%3},{%4,%5,%6,%7},{%8,%9},{%0,%1,%2,%3};" \
        : "+f"((d)[0]), "+f"((d)[1]), "+f"((d)[2]), "+f"((d)[3]) \
        : "r"(a0), "r"(a1), "r"(a2), "r"(a3), "r"(b0), "r"(b1))

__device__ __forceinline__ uint32_t smem_u32(const void* p) {
    uint32_t a;
    asm("{ .reg .u64 t; cvta.to.shared.u64 t, %1; cvt.u32.u64 %0, t; }" : "=r"(a) : "l"(p));
    return a;
}
__device__ __forceinline__ uint32_t pack2bf(float x, float y) {
    __nv_bfloat162 h = __floats2bfloat162_rn(x, y);
    return *(uint32_t*)&h;
}

__global__ __launch_bounds__(512, 1)
void gemm_mma(const float* __restrict__ A0, const float* __restrict__ Bt0,
              const float* __restrict__ bias0, void* __restrict__ C0, int M0, int mode0,
              const float* __restrict__ A1, const float* __restrict__ Bt1,
              const float* __restrict__ bias1, void* __restrict__ C1, int M1, int mode1,
              int nblk0, const float* __restrict__ w2)
{
    extern __shared__ char smem[];
    const uint32_t sbase = smem_u32(smem);
    const int tid   = threadIdx.x;
    const int wid   = tid >> 5;
    const int lane  = tid & 31;
    const int warpM = wid & 3;     // 4 warps along M (32 rows each)
    const int warpN = wid >> 2;    // 4 warps along N (32 cols each)

    const int sel = (blockIdx.x >= nblk0);
    const float* A    = sel ? A1 : A0;
    const float* Bt   = sel ? Bt1 : Bt0;
    const float* bias = sel ? bias1 : bias0;
    void* C           = sel ? C1 : C0;
    const int Mrows   = sel ? M1 : M0;
    const int mode    = sel ? mode1 : mode0;
    const int row0    = (sel ? (blockIdx.x - nblk0) : blockIdx.x) * 128;

    float* bias_s = (float*)(smem + SM_BIAS);
    float* w2_s   = (float*)(smem + SM_W2);
    if (tid < 128) {
        bias_s[tid] = bias[tid];
        if (mode == 2) w2_s[tid] = w2[tid];
    }

    // ---- prologue: fp32 -> bf16 hi/lo split into smem ----
#pragma unroll
    for (int idx = tid; idx < 4096; idx += 512) {
        int r  = idx >> 5;
        int kb = (idx & 31) * 4;
        float4 v = make_float4(0.f, 0.f, 0.f, 0.f);
        if (row0 + r < Mrows) v = *(const float4*)(A + (long)(row0 + r) * DH + kb);
        float hx = __bfloat162float(__float2bfloat16_rn(v.x));
        float hy = __bfloat162float(__float2bfloat16_rn(v.y));
        float hz = __bfloat162float(__float2bfloat16_rn(v.z));
        float hw = __bfloat162float(__float2bfloat16_rn(v.w));
        uint32_t off = r * STRB + kb * 2;
        *(uint2*)(smem + SM_A_HI + off) = make_uint2(pack2bf(hx, hy), pack2bf(hz, hw));
        *(uint2*)(smem + SM_A_LO + off) = make_uint2(pack2bf(v.x - hx, v.y - hy), pack2bf(v.z - hz, v.w - hw));
    }
#pragma unroll
    for (int idx = tid; idx < 4096; idx += 512) {
        int r  = idx >> 5;
        int kb = (idx & 31) * 4;
        float4 v = *(const float4*)(Bt + (long)r * DH + kb);
        float hx = __bfloat162float(__float2bfloat16_rn(v.x));
        float hy = __bfloat162float(__float2bfloat16_rn(v.y));
        float hz = __bfloat162float(__float2bfloat16_rn(v.z));
        float hw = __bfloat162float(__float2bfloat16_rn(v.w));
        uint32_t off = r * STRB + kb * 2;
        *(uint2*)(smem + SM_B_HI + off) = make_uint2(pack2bf(hx, hy), pack2bf(hz, hw));
        *(uint2*)(smem + SM_B_LO + off) = make_uint2(pack2bf(v.x - hx, v.y - hy), pack2bf(v.z - hz, v.w - hw));
    }
    __syncthreads();

    // ---- ldmatrix per-thread offsets ----
    const int grp = lane >> 3, r8 = lane & 7;
    uint32_t aoff[2];
#pragma unroll
    for (int i = 0; i < 2; i++) {
        int mrow = warpM * 32 + i * 16 + ((grp & 1) << 3) + r8;
        aoff[i] = (uint32_t)(mrow * STRB + ((grp >> 1) ? 16 : 0));
    }
    uint32_t boff[2];
#pragma unroll
    for (int jj = 0; jj < 2; jj++) {
        int nrow = warpN * 32 + jj * 16 + ((grp >> 1) << 3) + r8;
        boff[jj] = (uint32_t)(nrow * STRB + ((grp & 1) ? 16 : 0));
    }

    float acc[2][4][4];
#pragma unroll
    for (int i = 0; i < 2; i++)
#pragma unroll
        for (int j = 0; j < 4; j++)
#pragma unroll
            for (int q = 0; q < 4; q++) acc[i][j][q] = 0.f;

    // ---- main: 3 split terms x 8 k-steps ----
#pragma unroll
    for (int term = 0; term < 3; term++) {
        const uint32_t Ab = sbase + (term == 2 ? SM_A_LO : SM_A_HI);
        const uint32_t Bb = sbase + (term == 1 ? SM_B_LO : SM_B_HI);
#pragma unroll
        for (int ks = 0; ks < 8; ks++) {
            const uint32_t kb = ks * 32;
            uint32_t a[2][4];
#pragma unroll
            for (int i = 0; i < 2; i++)
                LDSM_X4(a[i][0], a[i][1], a[i][2], a[i][3], Ab + aoff[i] + kb);
            uint32_t b[2][4];
#pragma unroll
            for (int jj = 0; jj < 2; jj++)
                LDSM_X4(b[jj][0], b[jj][1], b[jj][2], b[jj][3], Bb + boff[jj] + kb);
#pragma unroll
            for (int i = 0; i < 2; i++)
#pragma unroll
                for (int j = 0; j < 4; j++)
                    MMA16816(acc[i][j], a[i][0], a[i][1], a[i][2], a[i][3],
                             b[j >> 1][(j & 1) * 2], b[j >> 1][(j & 1) * 2 + 1]);
        }
    }

    // ---- epilogue ----
    const int rbase = row0 + warpM * 32 + (lane >> 2);
    const int cbase = warpN * 32 + (lane & 3) * 2;
    if (mode == 2) {
        float* Cs = (float*)C;
        float dot[2][2] = {{0.f, 0.f}, {0.f, 0.f}};
#pragma unroll
        for (int i = 0; i < 2; i++)
#pragma unroll
            for (int j = 0; j < 4; j++) {
                int cc = cbase + j * 8;
                float b0 = bias_s[cc], b1 = bias_s[cc + 1];
                float w0 = w2_s[cc],   w1 = w2_s[cc + 1];
                dot[i][0] += fmaxf(acc[i][j][0] + b0, 0.f) * w0 + fmaxf(acc[i][j][1] + b1, 0.f) * w1;
                dot[i][1] += fmaxf(acc[i][j][2] + b0, 0.f) * w0 + fmaxf(acc[i][j][3] + b1, 0.f) * w1;
            }
#pragma unroll
        for (int i = 0; i < 2; i++)
#pragma unroll
            for (int hh = 0; hh < 2; hh++) {
                float v = dot[i][hh];
                v += __shfl_xor_sync(0xffffffffu, v, 1);
                v += __shfl_xor_sync(0xffffffffu, v, 2);
                int rr = rbase + i * 16 + hh * 8;
                if ((lane & 3) == 0 && rr < Mrows) atomicAdd(&Cs[rr], v);
            }
    } else if (mode == 3) {
        __half* Ch = (__half*)C;
#pragma unroll
        for (int i = 0; i < 2; i++)
#pragma unroll
            for (int j = 0; j < 4; j++) {
                int cc = cbase + j * 8;
                float b0 = bias_s[cc], b1 = bias_s[cc + 1];
                int rr = rbase + i * 16;
                if (rr < Mrows)
                    *(__half2*)(Ch + (long)rr * DH + cc) =
                        __floats2half2_rn(acc[i][j][0] + b0, acc[i][j][1] + b1);
                if (rr + 8 < Mrows)
                    *(__half2*)(Ch + (long)(rr + 8) * DH + cc) =
                        __floats2half2_rn(acc[i][j][2] + b0, acc[i][j][3] + b1);
            }
    } else {
        float* Cf = (float*)C;
#pragma unroll
        for (int i = 0; i < 2; i++)
#pragma unroll
            for (int j = 0; j < 4; j++) {
                int cc = cbase + j * 8;
                float b0 = bias_s[cc], b1 = bias_s[cc + 1];
                float v0 = acc[i][j][0] + b0, v1 = acc[i][j][1] + b1;
                float v2 = acc[i][j][2] + b0, v3 = acc[i][j][3] + b1;
                if (mode == 0) {
                    v0 = fmaxf(v0, 0.f); v1 = fmaxf(v1, 0.f);
                    v2 = fmaxf(v2, 0.f); v3 = fmaxf(v3, 0.f);
                }
                int rr = rbase + i * 16;
                if (rr < Mrows)     *(float2*)(Cf + (long)rr * DH + cc)       = make_float2(v0, v1);
                if (rr + 8 < Mrows) *(float2*)(Cf + (long)(rr + 8) * DH + cc) = make_float2(v2, v3);
            }
    }
}

// ---------------- edge aggregation (fp16 messages) + self loop + relu -------
__global__ void aggr_kernel(float* __restrict__ hout) {
    int node = (blockIdx.x * blockDim.x + threadIdx.x) >> 5;
    int lane = threadIdx.x & 31;
    if (node >= NN) return;
    int beg = g_off[node];
    int end = g_off[node + 1];
    float a0 = 0.f, a1 = 0.f, a2 = 0.f, a3 = 0.f;
    int e = beg;
    for (; e + 1 < end; e += 2) {
        int2 ed0 = g_edge[e];
        int2 ed1 = g_edge[e + 1];
        uint2 r0 = *(const uint2*)(g_Mh + (long)ed0.x * DH + lane * 4);
        uint2 r1 = *(const uint2*)(g_Mh + (long)ed1.x * DH + lane * 4);
        float w0 = __int_as_float(ed0.y), w1 = __int_as_float(ed1.y);
        float2 p0 = __half22float2(*(__half2*)&r0.x);
        float2 p1 = __half22float2(*(__half2*)&r0.y);
        float2 q0 = __half22float2(*(__half2*)&r1.x);
        float2 q1 = __half22float2(*(__half2*)&r1.y);
        a0 += w0 * p0.x + w1 * q0.x;
        a1 += w0 * p0.y + w1 * q0.y;
        a2 += w0 * p1.x + w1 * q1.x;
        a3 += w0 * p1.y + w1 * q1.y;
    }
    if (e < end) {
        int2 ed = g_edge[e];
        uint2 r0 = *(const uint2*)(g_Mh + (long)ed.x * DH + lane * 4);
        float w = __int_as_float(ed.y);
        float2 p0 = __half22float2(*(__half2*)&r0.x);
        float2 p1 = __half22float2(*(__half2*)&r0.y);
        a0 += w * p0.x; a1 += w * p0.y; a2 += w * p1.x; a3 += w * p1.y;
    }
    float4 sv = *(const float4*)(g_S + (long)node * DH + lane * 4);
    float4 h;
    h.x = fmaxf(a0 + sv.x, 0.f);
    h.y = fmaxf(a1 + sv.y, 0.f);
    h.z = fmaxf(a2 + sv.z, 0.f);
    h.w = fmaxf(a3 + sv.w, 0.f);
    *(float4*)(hout + (long)node * DH + lane * 4) = h;
}

// ---------------- softmax over layers + weighted sum ------------------------
// (score_b2 omitted: softmax over layers is shift-invariant)
__global__ void final_kernel(const float* __restrict__ stacked,
                             float* __restrict__ out, float* __restrict__ lw) {
    int node = (blockIdx.x * blockDim.x + threadIdx.x) >> 5;
    int lane = threadIdx.x & 31;
    if (node >= NN) return;
    float s0 = g_scores[node];
    float s1 = g_scores[NN + node];
    float s2 = g_scores[2 * NN + node];
    float m  = fmaxf(s0, fmaxf(s1, s2));
    float e0 = expf(s0 - m), e1 = expf(s1 - m), e2 = expf(s2 - m);
    float inv = 1.f / (e0 + e1 + e2);
    float w0 = e0 * inv, w1 = e1 * inv, w2 = e2 * inv;
    float4 a = *(const float4*)(stacked + (long)node * DH + lane * 4);
    float4 b = *(const float4*)(stacked + (long)NN * DH + (long)node * DH + lane * 4);
    float4 c = *(const float4*)(stacked + 2L * NN * DH + (long)node * DH + lane * 4);
    float4 o;
    o.x = w0 * a.x + w1 * b.x + w2 * c.x;
    o.y = w0 * a.y + w1 * b.y + w2 * c.y;
    o.z = w0 * a.z + w1 * b.z + w2 * c.z;
    o.w = w0 * a.w + w1 * b.w + w2 * c.w;
    *(float4*)(out + (long)node * DH + lane * 4) = o;
    if (lane == 0) {
        lw[node]          = w0;
        lw[NN + node]     = w1;
        lw[2 * NN + node] = w2;
    }
}

// ---------------- launch ----------------------------------------------------
extern "C" void kernel_launch(void* const* d_in, const int* in_sizes, int n_in,
                              void* d_out, int out_size) {
    const float* x       = (const float*)d_in[0];
    const int*   ei      = (const int*)  d_in[1];
    const float* conf    = (const float*)d_in[2];
    const float* msgb1   = (const float*)d_in[4];
    const float* msgb2   = (const float*)d_in[6];
    const float* selfb1  = (const float*)d_in[8];
    const float* selfb2  = (const float*)d_in[10];
    const float* scoreb1 = (const float*)d_in[12];
    const float* scoreW2 = (const float*)d_in[13];

    float* out     = (float*)d_out;                 // [NN, DH]
    float* stacked = out + (long)NN * DH;           // [NL, NN, DH]
    float* lw      = stacked + (long)NL * NN * DH;  // [NL, NN]

    void *p_tmpA, *p_tmpB, *p_Mh, *p_S, *p_Wt, *p_scores;
    cudaGetSymbolAddress(&p_tmpA, g_tmpA);
    cudaGetSymbolAddress(&p_tmpB, g_tmpB);
    cudaGetSymbolAddress(&p_Mh, g_Mh);
    cudaGetSymbolAddress(&p_S, g_S);
    cudaGetSymbolAddress(&p_Wt, g_Wt);
    cudaGetSymbolAddress(&p_scores, g_scores);
    float*  tmpA   = (float*)p_tmpA;
    float*  tmpB   = (float*)p_tmpB;
    __half* Mh     = (__half*)p_Mh;
    float*  Sn     = (float*)p_S;
    float*  Wt     = (float*)p_Wt;
    float*  scores = (float*)p_scores;

    cudaFuncSetAttribute(gemm_mma, cudaFuncAttributeMaxDynamicSharedMemorySize, SM_TOTAL);

    // CSR build + weight transpose + zero scores
    zero_kernel<<<(NL * NN + 255) / 256, 256>>>();
    count_kernel<<<(NE + 255) / 256, 256>>>(ei);
    transpose_weights<<<dim3(4, 4, 13), dim3(32, 8)>>>((const float*)d_in[3], (const float*)d_in[7],
                                                       (const float*)d_in[5], (const float*)d_in[9],
                                                       (const float*)d_in[11]);
    scan_kernel<<<1, 1024>>>();
    scatter_kernel<<<(NE + 255) / 256, 256>>>(ei, conf);

    const int GB = (NN + 127) / 128;  // 79 tiles per GEMM
    const float* hin = x;
    for (int i = 0; i < NL; i++) {
        // layer-1 pair: hin -> tmpA (msg), hin -> tmpB (self), both relu
        gemm_mma<<<2 * GB, 512, SM_TOTAL>>>(
            hin, Wt + (long)(0 + i) * DH * DH, msgb1  + i * DH, tmpA, NN, 0,
            hin, Wt + (long)(3 + i) * DH * DH, selfb1 + i * DH, tmpB, NN, 0, GB, nullptr);
        // layer-2 pair: tmpA -> Mh (fp16), tmpB -> Sn (fp32)
        gemm_mma<<<2 * GB, 512, SM_TOTAL>>>(
            tmpA, Wt + (long)(6 + i) * DH * DH, msgb2  + i * DH, Mh, NN, 3,
            tmpB, Wt + (long)(9 + i) * DH * DH, selfb2 + i * DH, Sn, NN, 1, GB, nullptr);
        float* hout = stacked + (long)i * NN * DH;
        aggr_kernel<<<(NN + 7) / 8, 256>>>(hout);
        hin = hout;
    }

    // scoring: fused Linear->ReLU->dot(W2) into GEMM epilogue
    const int GS = (NL * NN + 127) / 128;  // 235 tiles
    gemm_mma<<<GS, 512, SM_TOTAL>>>(
        stacked, Wt + 12L * DH * DH, scoreb1, scores, NL * NN, 2,
        stacked, Wt + 12L * DH * DH, scoreb1, scores, NL * NN, 2, GS, scoreW2);
    final_kernel<<<(NN + 7) / 8, 256>>>(stacked, out, lw);
}

// round 8
// speedup vs baseline: 1.0019x; 1.0019x over previous
#include <cuda_runtime.h>
#include <cuda_bf16.h>
#include <cuda_fp16.h>
#include <cstdint>
#include <math.h>

#define NN 10000
#define NE 640000
#define DH 128
#define NL 3

// ---------------- scratch (static device globals; no allocs) ----------------
__device__ int    g_cnt[NN];
__device__ int    g_off[NN + 1];
__device__ int    g_pos[NE];
__device__ int2   g_edge[NE];          // packed (src, w-as-bits), CSR order by dst
__device__ float  g_tmpA[NN * DH];
__device__ float  g_tmpB[NN * DH];
__device__ __half g_Mh[NN * DH];       // fp16 message buffer
__device__ float  g_S[NN * DH];
__device__ float  g_scores[NL * NN];
__device__ float  g_Wt[13 * DH * DH];  // pre-transposed weights: Wt[n][k] = W[k][n]

// ---------------- preprocessing ---------------------------------------------
__global__ void zero_kernel() {
    int i = blockIdx.x * blockDim.x + threadIdx.x;
    if (i < NN) g_cnt[i] = 0;
    if (i < NL * NN) g_scores[i] = 0.f;
}

__global__ void count_kernel(const int* __restrict__ ei) {
    int e = blockIdx.x * blockDim.x + threadIdx.x;
    if (e < NE) g_pos[e] = atomicAdd(&g_cnt[ei[NE + e]], 1);
}

// 1024 threads, 10 elems/thread: sequential + warp scan + cross-warp scan
__global__ void scan_kernel() {
    __shared__ int wsum[32];
    int t = threadIdx.x;
    int lane = t & 31, w = t >> 5;
    int base = t * 10;
    int loc[10];
    int s = 0;
#pragma unroll
    for (int i = 0; i < 10; i++) {
        int idx = base + i;
        int c = (idx < NN) ? g_cnt[idx] : 0;
        loc[i] = s; s += c;
    }
    int inc = s;
#pragma unroll
    for (int o = 1; o < 32; o <<= 1) {
        int u = __shfl_up_sync(0xffffffffu, inc, o);
        if (lane >= o) inc += u;
    }
    if (lane == 31) wsum[w] = inc;
    __syncthreads();
    if (w == 0) {
        int ws = wsum[lane];
#pragma unroll
        for (int o = 1; o < 32; o <<= 1) {
            int u = __shfl_up_sync(0xffffffffu, ws, o);
            if (lane >= o) ws += u;
        }
        wsum[lane] = ws;
    }
    __syncthreads();
    int warp_excl = (w == 0) ? 0 : wsum[w - 1];
    int excl = warp_excl + (inc - s);
#pragma unroll
    for (int i = 0; i < 10; i++) {
        int idx = base + i;
        if (idx < NN) g_off[idx] = excl + loc[i];
    }
    if (t == 1023) g_off[NN] = warp_excl + inc;
}

__global__ void scatter_kernel(const int* __restrict__ ei, const float* __restrict__ conf) {
    int e = blockIdx.x * blockDim.x + threadIdx.x;
    if (e >= NE) return;
    int s = ei[e];
    int d = ei[NE + e];
    float w = expf(-fabsf(conf[s] - conf[d]));
    int p = g_off[d] + g_pos[e];
    g_edge[p] = make_int2(s, __float_as_int(w));
}

// ---------------- weight pre-transpose: Wt[n][k] = W[k][n] ------------------
__global__ void transpose_weights(const float* __restrict__ msgW1, const float* __restrict__ selfW1,
                                  const float* __restrict__ msgW2, const float* __restrict__ selfW2,
                                  const float* __restrict__ scoreW1) {
    __shared__ float tile[32][33];
    int m = blockIdx.z;
    const float* src;
    if (m < 3)       src = msgW1  + (long)m * DH * DH;
    else if (m < 6)  src = selfW1 + (long)(m - 3) * DH * DH;
    else if (m < 9)  src = msgW2  + (long)(m - 6) * DH * DH;
    else if (m < 12) src = selfW2 + (long)(m - 9) * DH * DH;
    else             src = scoreW1;
    float* dst = g_Wt + (long)m * DH * DH;

    int x = blockIdx.x * 32 + threadIdx.x;
    int y = blockIdx.y * 32 + threadIdx.y;
#pragma unroll
    for (int j = 0; j < 32; j += 8)
        tile[threadIdx.y + j][threadIdx.x] = src[(y + j) * DH + x];
    __syncthreads();
    x = blockIdx.y * 32 + threadIdx.x;
    y = blockIdx.x * 32 + threadIdx.y;
#pragma unroll
    for (int j = 0; j < 32; j += 8)
        dst[(y + j) * DH + x] = tile[threadIdx.x][threadIdx.y + j];
}

// ================= fused dual-output mma.sync bf16 3x-split GEMM ============
// Two independent GEMMs in one launch (blockIdx < nblk0 -> half 0).
// C[M,128] = A[M,128] @ W[128,128] (+bias); Bt row-major [n][k] = W^T.
// mode 0: bias+relu fp32; mode 1: bias fp32; mode 2: relu(+bias) dot w2 -> scores (atomic);
// mode 3: bias fp16 store.
#define STRB 272
#define TILE_BYTES (128 * STRB)
#define SM_BIAS  0
#define SM_W2    512
#define SM_A_HI  1024
#define SM_A_LO  (SM_A_HI + TILE_BYTES)
#define SM_B_HI  (SM_A_LO + TILE_BYTES)
#define SM_B_LO  (SM_B_HI + TILE_BYTES)
#define SM_TOTAL (SM_B_LO + TILE_BYTES)

#define LDSM_X4(r0, r1, r2, r3, addr) \
    asm volatile("ldmatrix.sync.aligned.m8n8.x4.shared.b16 {%0,%1,%2,%3}, [%4];" \
        : "=r"(r0), "=r"(r1), "=r"(r2), "=r"(r3) : "r"(addr))

#define MMA16816(d, a0, a1, a2, a3, b0, b1) \
    asm volatile("mma.sync.aligned.m16n8k16.row.col.f32.bf16.bf16.f32 " \
        "{%0,%1,%2,%3},{%4,%5,%6,%7},{%8,%9},{%0,%1,%2,%3};" \
        : "+f"((d)[0]), "+f"((d)[1]), "+f"((d)[2]), "+f"((d)[3]) \
        : "r"(a0), "r"(a1), "r"(a2), "r"(a3), "r"(b0), "r"(b1))

__device__ __forceinline__ uint32_t smem_u32(const void* p) {
    uint32_t a;
    asm("{ .reg .u64 t; cvta.to.shared.u64 t, %1; cvt.u32.u64 %0, t; }" : "=r"(a) : "l"(p));
    return a;
}
__device__ __forceinline__ uint32_t pack2bf(float x, float y) {
    __nv_bfloat162 h = __floats2bfloat162_rn(x, y);
    return *(uint32_t*)&h;
}

__global__ __launch_bounds__(512, 1)
void gemm_mma(const float* __restrict__ A0, const float* __restrict__ Bt0,
              const float* __restrict__ bias0, void* __restrict__ C0, int M0, int mode0,
              const float* __restrict__ A1, const float* __restrict__ Bt1,
              const float* __restrict__ bias1, void* __restrict__ C1, int M1, int mode1,
              int nblk0, const float* __restrict__ w2)
{
    extern __shared__ char smem[];
    const uint32_t sbase = smem_u32(smem);
    const int tid   = threadIdx.x;
    const int wid   = tid >> 5;
    const int lane  = tid & 31;
    const int warpM = wid & 3;     // 4 warps along M (32 rows each)
    const int warpN = wid >> 2;    // 4 warps along N (32 cols each)

    const int sel = (blockIdx.x >= nblk0);
    const float* A    = sel ? A1 : A0;
    const float* Bt   = sel ? Bt1 : Bt0;
    const float* bias = sel ? bias1 : bias0;
    void* C           = sel ? C1 : C0;
    const int Mrows   = sel ? M1 : M0;
    const int mode    = sel ? mode1 : mode0;
    const int row0    = (sel ? (blockIdx.x - nblk0) : blockIdx.x) * 128;

    float* bias_s = (float*)(smem + SM_BIAS);
    float* w2_s   = (float*)(smem + SM_W2);
    if (tid < 128) {
        bias_s[tid] = bias[tid];
        if (mode == 2) w2_s[tid] = w2[tid];
    }

    // ---- prologue: fp32 -> bf16 hi/lo split into smem ----
#pragma unroll
    for (int idx = tid; idx < 4096; idx += 512) {
        int r  = idx >> 5;
        int kb = (idx & 31) * 4;
        float4 v = make_float4(0.f, 0.f, 0.f, 0.f);
        if (row0 + r < Mrows) v = *(const float4*)(A + (long)(row0 + r) * DH + kb);
        float hx = __bfloat162float(__float2bfloat16_rn(v.x));
        float hy = __bfloat162float(__float2bfloat16_rn(v.y));
        float hz = __bfloat162float(__float2bfloat16_rn(v.z));
        float hw = __bfloat162float(__float2bfloat16_rn(v.w));
        uint32_t off = r * STRB + kb * 2;
        *(uint2*)(smem + SM_A_HI + off) = make_uint2(pack2bf(hx, hy), pack2bf(hz, hw));
        *(uint2*)(smem + SM_A_LO + off) = make_uint2(pack2bf(v.x - hx, v.y - hy), pack2bf(v.z - hz, v.w - hw));
    }
#pragma unroll
    for (int idx = tid; idx < 4096; idx += 512) {
        int r  = idx >> 5;
        int kb = (idx & 31) * 4;
        float4 v = *(const float4*)(Bt + (long)r * DH + kb);
        float hx = __bfloat162float(__float2bfloat16_rn(v.x));
        float hy = __bfloat162float(__float2bfloat16_rn(v.y));
        float hz = __bfloat162float(__float2bfloat16_rn(v.z));
        float hw = __bfloat162float(__float2bfloat16_rn(v.w));
        uint32_t off = r * STRB + kb * 2;
        *(uint2*)(smem + SM_B_HI + off) = make_uint2(pack2bf(hx, hy), pack2bf(hz, hw));
        *(uint2*)(smem + SM_B_LO + off) = make_uint2(pack2bf(v.x - hx, v.y - hy), pack2bf(v.z - hz, v.w - hw));
    }
    __syncthreads();

    // ---- ldmatrix per-thread offsets ----
    const int grp = lane >> 3, r8 = lane & 7;
    uint32_t aoff[2];
#pragma unroll
    for (int i = 0; i < 2; i++) {
        int mrow = warpM * 32 + i * 16 + ((grp & 1) << 3) + r8;
        aoff[i] = (uint32_t)(mrow * STRB + ((grp >> 1) ? 16 : 0));
    }
    uint32_t boff[2];
#pragma unroll
    for (int jj = 0; jj < 2; jj++) {
        int nrow = warpN * 32 + jj * 16 + ((grp >> 1) << 3) + r8;
        boff[jj] = (uint32_t)(nrow * STRB + ((grp & 1) ? 16 : 0));
    }

    float acc[2][4][4];
#pragma unroll
    for (int i = 0; i < 2; i++)
#pragma unroll
        for (int j = 0; j < 4; j++)
#pragma unroll
            for (int q = 0; q < 4; q++) acc[i][j][q] = 0.f;

    // ---- main: 3 split terms x 8 k-steps ----
#pragma unroll
    for (int term = 0; term < 3; term++) {
        const uint32_t Ab = sbase + (term == 2 ? SM_A_LO : SM_A_HI);
        const uint32_t Bb = sbase + (term == 1 ? SM_B_LO : SM_B_HI);
#pragma unroll
        for (int ks = 0; ks < 8; ks++) {
            const uint32_t kb = ks * 32;
            uint32_t a[2][4];
#pragma unroll
            for (int i = 0; i < 2; i++)
                LDSM_X4(a[i][0], a[i][1], a[i][2], a[i][3], Ab + aoff[i] + kb);
            uint32_t b[2][4];
#pragma unroll
            for (int jj = 0; jj < 2; jj++)
                LDSM_X4(b[jj][0], b[jj][1], b[jj][2], b[jj][3], Bb + boff[jj] + kb);
#pragma unroll
            for (int i = 0; i < 2; i++)
#pragma unroll
                for (int j = 0; j < 4; j++)
                    MMA16816(acc[i][j], a[i][0], a[i][1], a[i][2], a[i][3],
                             b[j >> 1][(j & 1) * 2], b[j >> 1][(j & 1) * 2 + 1]);
        }
    }

    // ---- epilogue ----
    const int rbase = row0 + warpM * 32 + (lane >> 2);
    const int cbase = warpN * 32 + (lane & 3) * 2;
    if (mode == 2) {
        float* Cs = (float*)C;
        float dot[2][2] = {{0.f, 0.f}, {0.f, 0.f}};
#pragma unroll
        for (int i = 0; i < 2; i++)
#pragma unroll
            for (int j = 0; j < 4; j++) {
                int cc = cbase + j * 8;
                float b0 = bias_s[cc], b1 = bias_s[cc + 1];
                float w0 = w2_s[cc],   w1 = w2_s[cc + 1];
                dot[i][0] += fmaxf(acc[i][j][0] + b0, 0.f) * w0 + fmaxf(acc[i][j][1] + b1, 0.f) * w1;
                dot[i][1] += fmaxf(acc[i][j][2] + b0, 0.f) * w0 + fmaxf(acc[i][j][3] + b1, 0.f) * w1;
            }
#pragma unroll
        for (int i = 0; i < 2; i++)
#pragma unroll
            for (int hh = 0; hh < 2; hh++) {
                float v = dot[i][hh];
                v += __shfl_xor_sync(0xffffffffu, v, 1);
                v += __shfl_xor_sync(0xffffffffu, v, 2);
                int rr = rbase + i * 16 + hh * 8;
                if ((lane & 3) == 0 && rr < Mrows) atomicAdd(&Cs[rr], v);
            }
    } else if (mode == 3) {
        __half* Ch = (__half*)C;
#pragma unroll
        for (int i = 0; i < 2; i++)
#pragma unroll
            for (int j = 0; j < 4; j++) {
                int cc = cbase + j * 8;
                float b0 = bias_s[cc], b1 = bias_s[cc + 1];
                int rr = rbase + i * 16;
                if (rr < Mrows)
                    *(__half2*)(Ch + (long)rr * DH + cc) =
                        __floats2half2_rn(acc[i][j][0] + b0, acc[i][j][1] + b1);
                if (rr + 8 < Mrows)
                    *(__half2*)(Ch + (long)(rr + 8) * DH + cc) =
                        __floats2half2_rn(acc[i][j][2] + b0, acc[i][j][3] + b1);
            }
    } else {
        float* Cf = (float*)C;
#pragma unroll
        for (int i = 0; i < 2; i++)
#pragma unroll
            for (int j = 0; j < 4; j++) {
                int cc = cbase + j * 8;
                float b0 = bias_s[cc], b1 = bias_s[cc + 1];
                float v0 = acc[i][j][0] + b0, v1 = acc[i][j][1] + b1;
                float v2 = acc[i][j][2] + b0, v3 = acc[i][j][3] + b1;
                if (mode == 0) {
                    v0 = fmaxf(v0, 0.f); v1 = fmaxf(v1, 0.f);
                    v2 = fmaxf(v2, 0.f); v3 = fmaxf(v3, 0.f);
                }
                int rr = rbase + i * 16;
                if (rr < Mrows)     *(float2*)(Cf + (long)rr * DH + cc)       = make_float2(v0, v1);
                if (rr + 8 < Mrows) *(float2*)(Cf + (long)(rr + 8) * DH + cc) = make_float2(v2, v3);
            }
    }
}

// ---------------- edge aggregation (fp16 messages) + self loop + relu -------
__global__ void aggr_kernel(float* __restrict__ hout) {
    int node = (blockIdx.x * blockDim.x + threadIdx.x) >> 5;
    int lane = threadIdx.x & 31;
    if (node >= NN) return;
    int beg = g_off[node];
    int end = g_off[node + 1];
    float a0 = 0.f, a1 = 0.f, a2 = 0.f, a3 = 0.f;
    int e = beg;
    for (; e + 1 < end; e += 2) {
        int2 ed0 = g_edge[e];
        int2 ed1 = g_edge[e + 1];
        uint2 r0 = *(const uint2*)(g_Mh + (long)ed0.x * DH + lane * 4);
        uint2 r1 = *(const uint2*)(g_Mh + (long)ed1.x * DH + lane * 4);
        float w0 = __int_as_float(ed0.y), w1 = __int_as_float(ed1.y);
        float2 p0 = __half22float2(*(__half2*)&r0.x);
        float2 p1 = __half22float2(*(__half2*)&r0.y);
        float2 q0 = __half22float2(*(__half2*)&r1.x);
        float2 q1 = __half22float2(*(__half2*)&r1.y);
        a0 += w0 * p0.x + w1 * q0.x;
        a1 += w0 * p0.y + w1 * q0.y;
        a2 += w0 * p1.x + w1 * q1.x;
        a3 += w0 * p1.y + w1 * q1.y;
    }
    if (e < end) {
        int2 ed = g_edge[e];
        uint2 r0 = *(const uint2*)(g_Mh + (long)ed.x * DH + lane * 4);
        float w = __int_as_float(ed.y);
        float2 p0 = __half22float2(*(__half2*)&r0.x);
        float2 p1 = __half22float2(*(__half2*)&r0.y);
        a0 += w * p0.x; a1 += w * p0.y; a2 += w * p1.x; a3 += w * p1.y;
    }
    float4 sv = *(const float4*)(g_S + (long)node * DH + lane * 4);
    float4 h;
    h.x = fmaxf(a0 + sv.x, 0.f);
    h.y = fmaxf(a1 + sv.y, 0.f);
    h.z = fmaxf(a2 + sv.z, 0.f);
    h.w = fmaxf(a3 + sv.w, 0.f);
    *(float4*)(hout + (long)node * DH + lane * 4) = h;
}

// ---------------- softmax over layers + weighted sum ------------------------
// (score_b2 omitted: softmax over layers is shift-invariant)
__global__ void final_kernel(const float* __restrict__ stacked,
                             float* __restrict__ out, float* __restrict__ lw) {
    int node = (blockIdx.x * blockDim.x + threadIdx.x) >> 5;
    int lane = threadIdx.x & 31;
    if (node >= NN) return;
    float s0 = g_scores[node];
    float s1 = g_scores[NN + node];
    float s2 = g_scores[2 * NN + node];
    float m  = fmaxf(s0, fmaxf(s1, s2));
    float e0 = expf(s0 - m), e1 = expf(s1 - m), e2 = expf(s2 - m);
    float inv = 1.f / (e0 + e1 + e2);
    float w0 = e0 * inv, w1 = e1 * inv, w2 = e2 * inv;
    float4 a = *(const float4*)(stacked + (long)node * DH + lane * 4);
    float4 b = *(const float4*)(stacked + (long)NN * DH + (long)node * DH + lane * 4);
    float4 c = *(const float4*)(stacked + 2L * NN * DH + (long)node * DH + lane * 4);
    float4 o;
    o.x = w0 * a.x + w1 * b.x + w2 * c.x;
    o.y = w0 * a.y + w1 * b.y + w2 * c.y;
    o.z = w0 * a.z + w1 * b.z + w2 * c.z;
    o.w = w0 * a.w + w1 * b.w + w2 * c.w;
    *(float4*)(out + (long)node * DH + lane * 4) = o;
    if (lane == 0) {
        lw[node]          = w0;
        lw[NN + node]     = w1;
        lw[2 * NN + node] = w2;
    }
}

// ---------------- launch ----------------------------------------------------
extern "C" void kernel_launch(void* const* d_in, const int* in_sizes, int n_in,
                              void* d_out, int out_size) {
    const float* x       = (const float*)d_in[0];
    const int*   ei      = (const int*)  d_in[1];
    const float* conf    = (const float*)d_in[2];
    const float* msgb1   = (const float*)d_in[4];
    const float* msgb2   = (const float*)d_in[6];
    const float* selfb1  = (const float*)d_in[8];
    const float* selfb2  = (const float*)d_in[10];
    const float* scoreb1 = (const float*)d_in[12];
    const float* scoreW2 = (const float*)d_in[13];

    float* out     = (float*)d_out;                 // [NN, DH]
    float* stacked = out + (long)NN * DH;           // [NL, NN, DH]
    float* lw      = stacked + (long)NL * NN * DH;  // [NL, NN]

    void *p_tmpA, *p_tmpB, *p_Mh, *p_S, *p_Wt, *p_scores;
    cudaGetSymbolAddress(&p_tmpA, g_tmpA);
    cudaGetSymbolAddress(&p_tmpB, g_tmpB);
    cudaGetSymbolAddress(&p_Mh, g_Mh);
    cudaGetSymbolAddress(&p_S, g_S);
    cudaGetSymbolAddress(&p_Wt, g_Wt);
    cudaGetSymbolAddress(&p_scores, g_scores);
    float*  tmpA   = (float*)p_tmpA;
    float*  tmpB   = (float*)p_tmpB;
    __half* Mh     = (__half*)p_Mh;
    float*  Sn     = (float*)p_S;
    float*  Wt     = (float*)p_Wt;
    float*  scores = (float*)p_scores;

    cudaFuncSetAttribute(gemm_mma, cudaFuncAttributeMaxDynamicSharedMemorySize, SM_TOTAL);

    // CSR build + weight transpose + zero scores
    zero_kernel<<<(NL * NN + 255) / 256, 256>>>();
    count_kernel<<<(NE + 255) / 256, 256>>>(ei);
    transpose_weights<<<dim3(4, 4, 13), dim3(32, 8)>>>((const float*)d_in[3], (const float*)d_in[7],
                                                       (const float*)d_in[5], (const float*)d_in[9],
                                                       (const float*)d_in[11]);
    scan_kernel<<<1, 1024>>>();
    scatter_kernel<<<(NE + 255) / 256, 256>>>(ei, conf);

    const int GB = (NN + 127) / 128;  // 79 tiles per GEMM
    const float* hin = x;
    for (int i = 0; i < NL; i++) {
        // layer-1 pair: hin -> tmpA (msg), hin -> tmpB (self), both relu
        gemm_mma<<<2 * GB, 512, SM_TOTAL>>>(
            hin, Wt + (long)(0 + i) * DH * DH, msgb1  + i * DH, tmpA, NN, 0,
            hin, Wt + (long)(3 + i) * DH * DH, selfb1 + i * DH, tmpB, NN, 0, GB, nullptr);
        // layer-2 pair: tmpA -> Mh (fp16), tmpB -> Sn (fp32)
        gemm_mma<<<2 * GB, 512, SM_TOTAL>>>(
            tmpA, Wt + (long)(6 + i) * DH * DH, msgb2  + i * DH, Mh, NN, 3,
            tmpB, Wt + (long)(9 + i) * DH * DH, selfb2 + i * DH, Sn, NN, 1, GB, nullptr);
        float* hout = stacked + (long)i * NN * DH;
        aggr_kernel<<<(NN + 7) / 8, 256>>>(hout);
        hin = hout;
    }

    // scoring: fused Linear->ReLU->dot(W2) into GEMM epilogue
    const int GS = (NL * NN + 127) / 128;  // 235 tiles
    gemm_mma<<<GS, 512, SM_TOTAL>>>(
        stacked, Wt + 12L * DH * DH, scoreb1, scores, NL * NN, 2,
        stacked, Wt + 12L * DH * DH, scoreb1, scores, NL * NN, 2, GS, scoreW2);
    final_kernel<<<(NN + 7) / 8, 256>>>(stacked, out, lw);
}

// round 9
// speedup vs baseline: 1.0093x; 1.0074x over previous
#include <cuda_runtime.h>
#include <cuda_bf16.h>
#include <cuda_fp16.h>
#include <cstdint>
#include <math.h>

#define NN 10000
#define NE 640000
#define DH 128
#define NL 3

// ---------------- scratch (static device globals; no allocs) ----------------
__device__ int    g_cnt[NN];
__device__ int    g_off[NN + 1];
__device__ int    g_pos[NE];
__device__ int2   g_edge[NE];          // packed (src, w-as-bits), CSR order by dst
__device__ float  g_tmpA[NN * DH];
__device__ float  g_tmpB[NN * DH];
__device__ __half g_Mh[NN * DH];       // fp16 message buffer
__device__ float  g_S[NN * DH];
__device__ float  g_scores[NL * NN];
__device__ float  g_Wt[13 * DH * DH];  // pre-transposed weights: Wt[n][k] = W[k][n]

// ---------------- preprocessing ---------------------------------------------
__global__ void zero_kernel() {
    int i = blockIdx.x * blockDim.x + threadIdx.x;
    if (i < NN) g_cnt[i] = 0;
    if (i < NL * NN) g_scores[i] = 0.f;
}

__global__ void count_kernel(const int* __restrict__ ei) {
    int e = blockIdx.x * blockDim.x + threadIdx.x;
    if (e < NE) g_pos[e] = atomicAdd(&g_cnt[ei[NE + e]], 1);
}

// 1024 threads, 10 elems/thread: sequential + warp scan + cross-warp scan
__global__ void scan_kernel() {
    __shared__ int wsum[32];
    int t = threadIdx.x;
    int lane = t & 31, w = t >> 5;
    int base = t * 10;
    int loc[10];
    int s = 0;
#pragma unroll
    for (int i = 0; i < 10; i++) {
        int idx = base + i;
        int c = (idx < NN) ? g_cnt[idx] : 0;
        loc[i] = s; s += c;
    }
    int inc = s;
#pragma unroll
    for (int o = 1; o < 32; o <<= 1) {
        int u = __shfl_up_sync(0xffffffffu, inc, o);
        if (lane >= o) inc += u;
    }
    if (lane == 31) wsum[w] = inc;
    __syncthreads();
    if (w == 0) {
        int ws = wsum[lane];
#pragma unroll
        for (int o = 1; o < 32; o <<= 1) {
            int u = __shfl_up_sync(0xffffffffu, ws, o);
            if (lane >= o) ws += u;
        }
        wsum[lane] = ws;
    }
    __syncthreads();
    int warp_excl = (w == 0) ? 0 : wsum[w - 1];
    int excl = warp_excl + (inc - s);
#pragma unroll
    for (int i = 0; i < 10; i++) {
        int idx = base + i;
        if (idx < NN) g_off[idx] = excl + loc[i];
    }
    if (t == 1023) g_off[NN] = warp_excl + inc;
}

__global__ void scatter_kernel(const int* __restrict__ ei, const float* __restrict__ conf) {
    int e = blockIdx.x * blockDim.x + threadIdx.x;
    if (e >= NE) return;
    int s = ei[e];
    int d = ei[NE + e];
    float w = expf(-fabsf(conf[s] - conf[d]));
    int p = g_off[d] + g_pos[e];
    g_edge[p] = make_int2(s, __float_as_int(w));
}

// ---------------- weight pre-transpose: Wt[n][k] = W[k][n] ------------------
__global__ void transpose_weights(const float* __restrict__ msgW1, const float* __restrict__ selfW1,
                                  const float* __restrict__ msgW2, const float* __restrict__ selfW2,
                                  const float* __restrict__ scoreW1) {
    __shared__ float tile[32][33];
    int m = blockIdx.z;
    const float* src;
    if (m < 3)       src = msgW1  + (long)m * DH * DH;
    else if (m < 6)  src = selfW1 + (long)(m - 3) * DH * DH;
    else if (m < 9)  src = msgW2  + (long)(m - 6) * DH * DH;
    else if (m < 12) src = selfW2 + (long)(m - 9) * DH * DH;
    else             src = scoreW1;
    float* dst = g_Wt + (long)m * DH * DH;

    int x = blockIdx.x * 32 + threadIdx.x;
    int y = blockIdx.y * 32 + threadIdx.y;
#pragma unroll
    for (int j = 0; j < 32; j += 8)
        tile[threadIdx.y + j][threadIdx.x] = src[(y + j) * DH + x];
    __syncthreads();
    x = blockIdx.y * 32 + threadIdx.x;
    y = blockIdx.x * 32 + threadIdx.y;
#pragma unroll
    for (int j = 0; j < 32; j += 8)
        dst[(y + j) * DH + x] = tile[threadIdx.x][threadIdx.y + j];
}

// ================= fused dual-output mma.sync bf16 3x-split GEMM ============
// Two independent GEMMs in one launch (blockIdx < nblk0 -> half 0).
// C[M,128] = A[M,128] @ W[128,128] (+bias); Bt row-major [n][k] = W^T.
// mode 0: bias+relu fp32; mode 1: bias fp32; mode 2: relu(+bias) dot w2 -> scores (atomic);
// mode 3: bias fp16 store.
#define STRB 272
#define TILE_BYTES (128 * STRB)
#define SM_BIAS  0
#define SM_W2    512
#define SM_A_HI  1024
#define SM_A_LO  (SM_A_HI + TILE_BYTES)
#define SM_B_HI  (SM_A_LO + TILE_BYTES)
#define SM_B_LO  (SM_B_HI + TILE_BYTES)
#define SM_TOTAL (SM_B_LO + TILE_BYTES)

#define LDSM_X4(r0, r1, r2, r3, addr) \
    asm volatile("ldmatrix.sync.aligned.m8n8.x4.shared.b16 {%0,%1,%2,%3}, [%4];" \
        : "=r"(r0), "=r"(r1), "=r"(r2), "=r"(r3) : "r"(addr))

#define MMA16816(d, a0, a1, a2, a3, b0, b1) \
    asm volatile("mma.sync.aligned.m16n8k16.row.col.f32.bf16.bf16.f32 " \
        "{%0,%1,%2,%3},{%4,%5,%6,%7},{%8,%9},{%0,%1,%2,%3};" \
        : "+f"((d)[0]), "+f"((d)[1]), "+f"((d)[2]), "+f"((d)[3]) \
        : "r"(a0), "r"(a1), "r"(a2), "r"(a3), "r"(b0), "r"(b1))

__device__ __forceinline__ uint32_t smem_u32(const void* p) {
    uint32_t a;
    asm("{ .reg .u64 t; cvta.to.shared.u64 t, %1; cvt.u32.u64 %0, t; }" : "=r"(a) : "l"(p));
    return a;
}
__device__ __forceinline__ uint32_t pack2bf(float x, float y) {
    __nv_bfloat162 h = __floats2bfloat162_rn(x, y);
    return *(uint32_t*)&h;
}

__global__ __launch_bounds__(512, 1)
void gemm_mma(const float* __restrict__ A0, const float* __restrict__ Bt0,
              const float* __restrict__ bias0, void* __restrict__ C0, int M0, int mode0,
              const float* __restrict__ A1, const float* __restrict__ Bt1,
              const float* __restrict__ bias1, void* __restrict__ C1, int M1, int mode1,
              int nblk0, const float* __restrict__ w2)
{
    extern __shared__ char smem[];
    const uint32_t sbase = smem_u32(smem);
    const int tid   = threadIdx.x;
    const int wid   = tid >> 5;
    const int lane  = tid & 31;
    const int warpM = wid & 3;     // 4 warps along M (32 rows each)
    const int warpN = wid >> 2;    // 4 warps along N (32 cols each)

    const int sel = (blockIdx.x >= nblk0);
    const float* A    = sel ? A1 : A0;
    const float* Bt   = sel ? Bt1 : Bt0;
    const float* bias = sel ? bias1 : bias0;
    void* C           = sel ? C1 : C0;
    const int Mrows   = sel ? M1 : M0;
    const int mode    = sel ? mode1 : mode0;
    const int row0    = (sel ? (blockIdx.x - nblk0) : blockIdx.x) * 128;

    float* bias_s = (float*)(smem + SM_BIAS);
    float* w2_s   = (float*)(smem + SM_W2);
    if (tid < 128) {
        bias_s[tid] = bias[tid];
        if (mode == 2) w2_s[tid] = w2[tid];
    }

    // ---- prologue: fp32 -> bf16 hi/lo split into smem ----
#pragma unroll
    for (int idx = tid; idx < 4096; idx += 512) {
        int r  = idx >> 5;
        int kb = (idx & 31) * 4;
        float4 v = make_float4(0.f, 0.f, 0.f, 0.f);
        if (row0 + r < Mrows) v = *(const float4*)(A + (long)(row0 + r) * DH + kb);
        float hx = __bfloat162float(__float2bfloat16_rn(v.x));
        float hy = __bfloat162float(__float2bfloat16_rn(v.y));
        float hz = __bfloat162float(__float2bfloat16_rn(v.z));
        float hw = __bfloat162float(__float2bfloat16_rn(v.w));
        uint32_t off = r * STRB + kb * 2;
        *(uint2*)(smem + SM_A_HI + off) = make_uint2(pack2bf(hx, hy), pack2bf(hz, hw));
        *(uint2*)(smem + SM_A_LO + off) = make_uint2(pack2bf(v.x - hx, v.y - hy), pack2bf(v.z - hz, v.w - hw));
    }
#pragma unroll
    for (int idx = tid; idx < 4096; idx += 512) {
        int r  = idx >> 5;
        int kb = (idx & 31) * 4;
        float4 v = *(const float4*)(Bt + (long)r * DH + kb);
        float hx = __bfloat162float(__float2bfloat16_rn(v.x));
        float hy = __bfloat162float(__float2bfloat16_rn(v.y));
        float hz = __bfloat162float(__float2bfloat16_rn(v.z));
        float hw = __bfloat162float(__float2bfloat16_rn(v.w));
        uint32_t off = r * STRB + kb * 2;
        *(uint2*)(smem + SM_B_HI + off) = make_uint2(pack2bf(hx, hy), pack2bf(hz, hw));
        *(uint2*)(smem + SM_B_LO + off) = make_uint2(pack2bf(v.x - hx, v.y - hy), pack2bf(v.z - hz, v.w - hw));
    }
    __syncthreads();

    // ---- ldmatrix per-thread offsets ----
    const int grp = lane >> 3, r8 = lane & 7;
    uint32_t aoff[2];
#pragma unroll
    for (int i = 0; i < 2; i++) {
        int mrow = warpM * 32 + i * 16 + ((grp & 1) << 3) + r8;
        aoff[i] = (uint32_t)(mrow * STRB + ((grp >> 1) ? 16 : 0));
    }
    uint32_t boff[2];
#pragma unroll
    for (int jj = 0; jj < 2; jj++) {
        int nrow = warpN * 32 + jj * 16 + ((grp >> 1) << 3) + r8;
        boff[jj] = (uint32_t)(nrow * STRB + ((grp & 1) ? 16 : 0));
    }

    float acc[2][4][4];
#pragma unroll
    for (int i = 0; i < 2; i++)
#pragma unroll
        for (int j = 0; j < 4; j++)
#pragma unroll
            for (int q = 0; q < 4; q++) acc[i][j][q] = 0.f;

    // ---- main: 3 split terms x 8 k-steps ----
#pragma unroll
    for (int term = 0; term < 3; term++) {
        const uint32_t Ab = sbase + (term == 2 ? SM_A_LO : SM_A_HI);
        const uint32_t Bb = sbase + (term == 1 ? SM_B_LO : SM_B_HI);
#pragma unroll
        for (int ks = 0; ks < 8; ks++) {
            const uint32_t kb = ks * 32;
            uint32_t a[2][4];
#pragma unroll
            for (int i = 0; i < 2; i++)
                LDSM_X4(a[i][0], a[i][1], a[i][2], a[i][3], Ab + aoff[i] + kb);
            uint32_t b[2][4];
#pragma unroll
            for (int jj = 0; jj < 2; jj++)
                LDSM_X4(b[jj][0], b[jj][1], b[jj][2], b[jj][3], Bb + boff[jj] + kb);
#pragma unroll
            for (int i = 0; i < 2; i++)
#pragma unroll
                for (int j = 0; j < 4; j++)
                    MMA16816(acc[i][j], a[i][0], a[i][1], a[i][2], a[i][3],
                             b[j >> 1][(j & 1) * 2], b[j >> 1][(j & 1) * 2 + 1]);
        }
    }

    // ---- epilogue ----
    const int rbase = row0 + warpM * 32 + (lane >> 2);
    const int cbase = warpN * 32 + (lane & 3) * 2;
    if (mode == 2) {
        float* Cs = (float*)C;
        float dot[2][2] = {{0.f, 0.f}, {0.f, 0.f}};
#pragma unroll
        for (int i = 0; i < 2; i++)
#pragma unroll
            for (int j = 0; j < 4; j++) {
                int cc = cbase + j * 8;
                float b0 = bias_s[cc], b1 = bias_s[cc + 1];
                float w0 = w2_s[cc],   w1 = w2_s[cc + 1];
                dot[i][0] += fmaxf(acc[i][j][0] + b0, 0.f) * w0 + fmaxf(acc[i][j][1] + b1, 0.f) * w1;
                dot[i][1] += fmaxf(acc[i][j][2] + b0, 0.f) * w0 + fmaxf(acc[i][j][3] + b1, 0.f) * w1;
            }
#pragma unroll
        for (int i = 0; i < 2; i++)
#pragma unroll
            for (int hh = 0; hh < 2; hh++) {
                float v = dot[i][hh];
                v += __shfl_xor_sync(0xffffffffu, v, 1);
                v += __shfl_xor_sync(0xffffffffu, v, 2);
                int rr = rbase + i * 16 + hh * 8;
                if ((lane & 3) == 0 && rr < Mrows) atomicAdd(&Cs[rr], v);
            }
    } else if (mode == 3) {
        __half* Ch = (__half*)C;
#pragma unroll
        for (int i = 0; i < 2; i++)
#pragma unroll
            for (int j = 0; j < 4; j++) {
                int cc = cbase + j * 8;
                float b0 = bias_s[cc], b1 = bias_s[cc + 1];
                int rr = rbase + i * 16;
                if (rr < Mrows)
                    *(__half2*)(Ch + (long)rr * DH + cc) =
                        __floats2half2_rn(acc[i][j][0] + b0, acc[i][j][1] + b1);
                if (rr + 8 < Mrows)
                    *(__half2*)(Ch + (long)(rr + 8) * DH + cc) =
                        __floats2half2_rn(acc[i][j][2] + b0, acc[i][j][3] + b1);
            }
    } else {
        float* Cf = (float*)C;
#pragma unroll
        for (int i = 0; i < 2; i++)
#pragma unroll
            for (int j = 0; j < 4; j++) {
                int cc = cbase + j * 8;
                float b0 = bias_s[cc], b1 = bias_s[cc + 1];
                float v0 = acc[i][j][0] + b0, v1 = acc[i][j][1] + b1;
                float v2 = acc[i][j][2] + b0, v3 = acc[i][j][3] + b1;
                if (mode == 0) {
                    v0 = fmaxf(v0, 0.f); v1 = fmaxf(v1, 0.f);
                    v2 = fmaxf(v2, 0.f); v3 = fmaxf(v3, 0.f);
                }
                int rr = rbase + i * 16;
                if (rr < Mrows)     *(float2*)(Cf + (long)rr * DH + cc)       = make_float2(v0, v1);
                if (rr + 8 < Mrows) *(float2*)(Cf + (long)(rr + 8) * DH + cc) = make_float2(v2, v3);
            }
    }
}

// ---------------- edge aggregation (fp16 messages) + self loop + relu -------
__global__ void aggr_kernel(float* __restrict__ hout) {
    int node = (blockIdx.x * blockDim.x + threadIdx.x) >> 5;
    int lane = threadIdx.x & 31;
    if (node >= NN) return;
    int beg = g_off[node];
    int end = g_off[node + 1];
    float a0 = 0.f, a1 = 0.f, a2 = 0.f, a3 = 0.f;
    int e = beg;
    for (; e + 1 < end; e += 2) {
        int2 ed0 = g_edge[e];
        int2 ed1 = g_edge[e + 1];
        uint2 r0 = *(const uint2*)(g_Mh + (long)ed0.x * DH + lane * 4);
        uint2 r1 = *(const uint2*)(g_Mh + (long)ed1.x * DH + lane * 4);
        float w0 = __int_as_float(ed0.y), w1 = __int_as_float(ed1.y);
        float2 p0 = __half22float2(*(__half2*)&r0.x);
        float2 p1 = __half22float2(*(__half2*)&r0.y);
        float2 q0 = __half22float2(*(__half2*)&r1.x);
        float2 q1 = __half22float2(*(__half2*)&r1.y);
        a0 += w0 * p0.x + w1 * q0.x;
        a1 += w0 * p0.y + w1 * q0.y;
        a2 += w0 * p1.x + w1 * q1.x;
        a3 += w0 * p1.y + w1 * q1.y;
    }
    if (e < end) {
        int2 ed = g_edge[e];
        uint2 r0 = *(const uint2*)(g_Mh + (long)ed.x * DH + lane * 4);
        float w = __int_as_float(ed.y);
        float2 p0 = __half22float2(*(__half2*)&r0.x);
        float2 p1 = __half22float2(*(__half2*)&r0.y);
        a0 += w * p0.x; a1 += w * p0.y; a2 += w * p1.x; a3 += w * p1.y;
    }
    float4 sv = *(const float4*)(g_S + (long)node * DH + lane * 4);
    float4 h;
    h.x = fmaxf(a0 + sv.x, 0.f);
    h.y = fmaxf(a1 + sv.y, 0.f);
    h.z = fmaxf(a2 + sv.z, 0.f);
    h.w = fmaxf(a3 + sv.w, 0.f);
    *(float4*)(hout + (long)node * DH + lane * 4) = h;
}

// ---------------- softmax over layers + weighted sum ------------------------
// (score_b2 omitted: softmax over layers is shift-invariant)
__global__ void final_kernel(const float* __restrict__ stacked,
                             float* __restrict__ out, float* __restrict__ lw) {
    int node = (blockIdx.x * blockDim.x + threadIdx.x) >> 5;
    int lane = threadIdx.x & 31;
    if (node >= NN) return;
    float s0 = g_scores[node];
    float s1 = g_scores[NN + node];
    float s2 = g_scores[2 * NN + node];
    float m  = fmaxf(s0, fmaxf(s1, s2));
    float e0 = expf(s0 - m), e1 = expf(s1 - m), e2 = expf(s2 - m);
    float inv = 1.f / (e0 + e1 + e2);
    float w0 = e0 * inv, w1 = e1 * inv, w2 = e2 * inv;
    float4 a = *(const float4*)(stacked + (long)node * DH + lane * 4);
    float4 b = *(const float4*)(stacked + (long)NN * DH + (long)node * DH + lane * 4);
    float4 c = *(const float4*)(stacked + 2L * NN * DH + (long)node * DH + lane * 4);
    float4 o;
    o.x = w0 * a.x + w1 * b.x + w2 * c.x;
    o.y = w0 * a.y + w1 * b.y + w2 * c.y;
    o.z = w0 * a.z + w1 * b.z + w2 * c.z;
    o.w = w0 * a.w + w1 * b.w + w2 * c.w;
    *(float4*)(out + (long)node * DH + lane * 4) = o;
    if (lane == 0) {
        lw[node]          = w0;
        lw[NN + node]     = w1;
        lw[2 * NN + node] = w2;
    }
}

// ---------------- launch ----------------------------------------------------
extern "C" void kernel_launch(void* const* d_in, const int* in_sizes, int n_in,
                              void* d_out, int out_size) {
    const float* x       = (const float*)d_in[0];
    const int*   ei      = (const int*)  d_in[1];
    const float* conf    = (const float*)d_in[2];
    const float* msgb1   = (const float*)d_in[4];
    const float* msgb2   = (const float*)d_in[6];
    const float* selfb1  = (const float*)d_in[8];
    const float* selfb2  = (const float*)d_in[10];
    const float* scoreb1 = (const float*)d_in[12];
    const float* scoreW2 = (const float*)d_in[13];

    float* out     = (float*)d_out;                 // [NN, DH]
    float* stacked = out + (long)NN * DH;           // [NL, NN, DH]
    float* lw      = stacked + (long)NL * NN * DH;  // [NL, NN]

    void *p_tmpA, *p_tmpB, *p_Mh, *p_S, *p_Wt, *p_scores;
    cudaGetSymbolAddress(&p_tmpA, g_tmpA);
    cudaGetSymbolAddress(&p_tmpB, g_tmpB);
    cudaGetSymbolAddress(&p_Mh, g_Mh);
    cudaGetSymbolAddress(&p_S, g_S);
    cudaGetSymbolAddress(&p_Wt, g_Wt);
    cudaGetSymbolAddress(&p_scores, g_scores);
    float*  tmpA   = (float*)p_tmpA;
    float*  tmpB   = (float*)p_tmpB;
    __half* Mh     = (__half*)p_Mh;
    float*  Sn     = (float*)p_S;
    float*  Wt     = (float*)p_Wt;
    float*  scores = (float*)p_scores;

    cudaFuncSetAttribute(gemm_mma, cudaFuncAttributeMaxDynamicSharedMemorySize, SM_TOTAL);

    // CSR build + weight transpose + zero scores
    zero_kernel<<<(NL * NN + 255) / 256, 256>>>();
    count_kernel<<<(NE + 255) / 256, 256>>>(ei);
    transpose_weights<<<dim3(4, 4, 13), dim3(32, 8)>>>((const float*)d_in[3], (const float*)d_in[7],
                                                       (const float*)d_in[5], (const float*)d_in[9],
                                                       (const float*)d_in[11]);
    scan_kernel<<<1, 1024>>>();
    scatter_kernel<<<(NE + 255) / 256, 256>>>(ei, conf);

    const int GB = (NN + 127) / 128;  // 79 tiles per GEMM
    const float* hin = x;
    for (int i = 0; i < NL; i++) {
        // layer-1 pair: hin -> tmpA (msg), hin -> tmpB (self), both relu
        gemm_mma<<<2 * GB, 512, SM_TOTAL>>>(
            hin, Wt + (long)(0 + i) * DH * DH, msgb1  + i * DH, tmpA, NN, 0,
            hin, Wt + (long)(3 + i) * DH * DH, selfb1 + i * DH, tmpB, NN, 0, GB, nullptr);
        // layer-2 pair: tmpA -> Mh (fp16), tmpB -> Sn (fp32)
        gemm_mma<<<2 * GB, 512, SM_TOTAL>>>(
            tmpA, Wt + (long)(6 + i) * DH * DH, msgb2  + i * DH, Mh, NN, 3,
            tmpB, Wt + (long)(9 + i) * DH * DH, selfb2 + i * DH, Sn, NN, 1, GB, nullptr);
        float* hout = stacked + (long)i * NN * DH;
        aggr_kernel<<<(NN + 7) / 8, 256>>>(hout);
        hin = hout;
    }

    // scoring: fused Linear->ReLU->dot(W2) into GEMM epilogue
    const int GS = (NL * NN + 127) / 128;  // 235 tiles
    gemm_mma<<<GS, 512, SM_TOTAL>>>(
        stacked, Wt + 12L * DH * DH, scoreb1, scores, NL * NN, 2,
        stacked, Wt + 12L * DH * DH, scoreb1, scores, NL * NN, 2, GS, scoreW2);
    final_kernel<<<(NN + 7) / 8, 256>>>(stacked, out, lw);
}